// round 9
// baseline (speedup 1.0000x reference)
#include <cuda_runtime.h>

#define NMAX 100000
#define D 32
#define MAXB 2048

// ---- persistent scratch (device globals; zero-initialized at load) ----
__device__ float    d_q[NMAX];        // q[n] = dinv[n] * (u . p[n] + c2)
__device__ float    d_sacc[NMAX];     // scalar accumulator, init = q (self loop)
__device__ float    d_dinv[NMAX];
__device__ int      d_deg[NMAX];      // starts 0; P2 re-zeroes after read
__device__ double   d_part[MAXB][5];  // per-block x-moment partials
__device__ unsigned d_count;          // barrier arrive counter (returns to 0)
__device__ unsigned d_epoch;          // monotonic barrier epoch (replay-safe)

// epoch-based grid barrier: wait until (epoch - base) >= tgt.
// base is read by every block BEFORE its first arrive; epoch can only advance
// after ALL blocks arrived, hence after all have read base -> race-free, and
// monotonic epoch makes it safe across CUDA-graph replays.
__device__ __forceinline__ void gbar(unsigned base, unsigned tgt, unsigned nb) {
    __syncthreads();
    if (threadIdx.x == 0) {
        __threadfence();
        if (atomicAdd(&d_count, 1) == nb - 1) {
            atomicExch(&d_count, 0);
            __threadfence();
            atomicAdd(&d_epoch, 1);
        } else {
            while (atomicAdd(&d_epoch, 0) - base < tgt) __nanosleep(64);
        }
    }
    __syncthreads();
}

__global__ void __launch_bounds__(256, 4) fused_k(
    const float* __restrict__ x, const int* __restrict__ ei,
    const float* __restrict__ w1, const float* __restrict__ b1,
    const float* __restrict__ gam, const float* __restrict__ bet,
    const float* __restrict__ pa,
    const float* __restrict__ w2, const float* __restrict__ b2,
    const float* __restrict__ gw, const float* __restrict__ gb,
    const float* __restrict__ wb, const float* __restrict__ bb,
    float* __restrict__ out, int n, int E) {
    __shared__ float sA[2 * D], sB[D], sU[D], sV[D];
    __shared__ float sc2, sC;
    __shared__ double sst[5];
    __shared__ unsigned sbase;
    __shared__ double sred[8][5];

    const int t = threadIdx.x;
    const unsigned nb = gridDim.x;
    const int g = blockIdx.x * 256 + t;
    const int T = nb * 256;
    const int nE4 = E >> 2;
    const int Etail = E & 3;

    if (t == 0) sbase = atomicAdd(&d_epoch, 0);
    __syncthreads();
    const unsigned base = sbase;

    // ---------------- P1: in-degree histogram + x moments ----------------
    {
        const int4* dst4 = (const int4*)(ei + E);
        for (int i = g; i < nE4; i += T) {
            int4 d = dst4[i];
            atomicAdd(&d_deg[d.x], 1);
            atomicAdd(&d_deg[d.y], 1);
            atomicAdd(&d_deg[d.z], 1);
            atomicAdd(&d_deg[d.w], 1);
        }
        if (g == 0)
            for (int k = 0; k < Etail; k++) atomicAdd(&d_deg[ei[E + nE4 * 4 + k]], 1);

        float s[5] = { 0.f, 0.f, 0.f, 0.f, 0.f };
        for (int i = g; i < n; i += T) {
            float2 xv = ((const float2*)x)[i];
            s[0] += xv.x; s[1] += xv.y;
            s[2] += xv.x * xv.x; s[3] += xv.y * xv.y; s[4] += xv.x * xv.y;
        }
#pragma unroll
        for (int o = 16; o; o >>= 1)
#pragma unroll
            for (int j = 0; j < 5; j++) s[j] += __shfl_xor_sync(0xffffffffu, s[j], o);
        if ((t & 31) == 0)
#pragma unroll
            for (int j = 0; j < 5; j++) sred[t >> 5][j] = (double)s[j];
        __syncthreads();
        if (t < 5) {
            double acc = 0.0;
#pragma unroll
            for (int w = 0; w < 8; w++) acc += sred[w][t];
            d_part[blockIdx.x][t] = acc;
        }
    }
    gbar(base, 1, nb);

    // ---------------- P2: fold constants + encode q ----------------
    {
        // every block reduces the partials itself (5 warps, strided)
        if (t < 160) {
            int c = t >> 5, k = t & 31;
            double a = 0.0;
            for (unsigned b = k; b < nb; b += 32) a += d_part[b][c];
#pragma unroll
            for (int o = 16; o; o >>= 1) a += __shfl_xor_sync(0xffffffffu, a, o);
            if (k == 0) sst[c] = a;
        }
        __syncthreads();
        if (t < D) {
            double invN = 1.0 / (double)n;
            double m0 = sst[0] * invN, m1 = sst[1] * invN;
            double v00 = sst[2] * invN - m0 * m0;
            double v11 = sst[3] * invN - m1 * m1;
            double v01 = sst[4] * invN - m0 * m1;
            float a0 = w1[2 * t], a1 = w1[2 * t + 1];
            float mean = (float)((double)a0 * m0 + (double)a1 * m1) + b1[t];
            float var  = (float)((double)a0 * a0 * v00 + 2.0 * (double)a0 * a1 * v01 +
                                 (double)a1 * a1 * v11);
            float scale = gam[t] * rsqrtf(var + 1e-5f);
            sA[2 * t]     = a0 * scale;
            sA[2 * t + 1] = a1 * scale;
            sB[t] = b1[t] * scale + bet[t] - mean * scale;
            float v = 0.f;
#pragma unroll
            for (int r = 0; r < D; r++) v = fmaf(wb[r], gw[r * D + t], v);
            sV[t] = v;
        }
        __syncthreads();
        if (t < D) {
            float u = 0.f;
#pragma unroll
            for (int r = 0; r < D; r++) u = fmaf(sV[r], w2[r * D + t], u);
            sU[t] = u;
            float cc = sV[t] * b2[t];
            float Cc = wb[t] * gb[t];
#pragma unroll
            for (int o = 16; o; o >>= 1) {
                cc += __shfl_xor_sync(0xffffffffu, cc, o);
                Cc += __shfl_xor_sync(0xffffffffu, Cc, o);
            }
            if (t == 0) { sc2 = cc; sC = Cc + bb[0]; }
        }
        __syncthreads();

        float alpha = pa[0];
        for (int node = g; node < n; node += T) {
            float2 xv = ((const float2*)x)[node];
            int dg = __ldcg(&d_deg[node]);   // written by RED in L2 only
            d_deg[node] = 0;                 // re-zero for next replay
            float dv = rsqrtf((float)dg + 1.0f);
            float acc = sc2;
#pragma unroll
            for (int k = 0; k < D; k++) {
                float h = fmaf(sA[2 * k], xv.x, fmaf(sA[2 * k + 1], xv.y, sB[k]));
                float p = h >= 0.f ? h : alpha * h;
                acc = fmaf(sU[k], p, acc);
            }
            float qv = dv * acc;
            d_q[node] = qv;
            d_sacc[node] = qv;               // self-loop prefolded
            d_dinv[node] = dv;
        }
    }
    gbar(base, 2, nb);

    // ---------------- P3: edge scatter ----------------
    {
        const int4* s4 = (const int4*)ei;
        const int4* t4 = (const int4*)(ei + E);   // L2-hot from P1
        for (int i = g; i < nE4; i += T) {
            int4 ss = s4[i];
            int4 dd = t4[i];
            float q0 = __ldg(&d_q[ss.x]);
            float q1 = __ldg(&d_q[ss.y]);
            float q2 = __ldg(&d_q[ss.z]);
            float q3 = __ldg(&d_q[ss.w]);
            atomicAdd(&d_sacc[dd.x], q0);
            atomicAdd(&d_sacc[dd.y], q1);
            atomicAdd(&d_sacc[dd.z], q2);
            atomicAdd(&d_sacc[dd.w], q3);
        }
        if (g == 0)
            for (int k = 0; k < Etail; k++) {
                int e = nE4 * 4 + k;
                atomicAdd(&d_sacc[ei[E + e]], __ldg(&d_q[ei[e]]));
            }
    }
    gbar(base, 3, nb);

    // ---------------- P4: score ----------------
    {
        float C = sC;
        int n4 = n >> 2;
        for (int i = g; i < n4; i += T) {
            float4 dv = ((const float4*)d_dinv)[i];
            // sacc was plain-stored in P2 (lives in some L1) then RED-updated
            // in L2 during P3 -> MUST bypass L1 here.
            float s0 = __ldcg(&d_sacc[4 * i]);
            float s1 = __ldcg(&d_sacc[4 * i + 1]);
            float s2 = __ldcg(&d_sacc[4 * i + 2]);
            float s3 = __ldcg(&d_sacc[4 * i + 3]);
            float4 o;
            o.x = fmaf(dv.x, s0, C);
            o.y = fmaf(dv.y, s1, C);
            o.z = fmaf(dv.z, s2, C);
            o.w = fmaf(dv.w, s3, C);
            ((float4*)out)[i] = o;
        }
        if (g == 0)
            for (int k = n4 * 4; k < n; k++)
                out[k] = fmaf(d_dinv[k], __ldcg(&d_sacc[k]), C);
    }
}

// ---------------------------------------------------------------------------
extern "C" void kernel_launch(void* const* d_in, const int* in_sizes, int n_in,
                              void* d_out, int out_size) {
    const float* x   = (const float*)d_in[0];
    const int*   ei  = (const int*)d_in[1];      // int32 (JAX x64 disabled)
    const float* w1  = (const float*)d_in[2];
    const float* b1  = (const float*)d_in[3];
    const float* gam = (const float*)d_in[4];
    const float* bet = (const float*)d_in[5];
    const float* pa  = (const float*)d_in[6];
    const float* w2  = (const float*)d_in[7];
    const float* b2  = (const float*)d_in[8];
    const float* gw  = (const float*)d_in[9];
    const float* gb  = (const float*)d_in[10];
    const float* wb  = (const float*)d_in[11];
    const float* bb  = (const float*)d_in[12];
    int n = in_sizes[0] / 2;
    int E = in_sizes[1] / 2;

    int dev = 0, sms = 148;
    cudaGetDevice(&dev);
    cudaDeviceGetAttribute(&sms, cudaDevAttrMultiProcessorCount, dev);
    int nb = sms * 4;                  // co-residency guaranteed by launch_bounds
    if (nb > MAXB) nb = MAXB;

    fused_k<<<nb, 256>>>(x, ei, w1, b1, gam, bet, pa, w2, b2, gw, gb, wb, bb,
                         (float*)d_out, n, E);
}

// round 10
// speedup vs baseline: 1.2640x; 1.2640x over previous
#include <cuda_runtime.h>

#define NMAX 100000
#define D 32
#define NBN ((NMAX + 255) / 256)   // 391 node-blocks

// ---- persistent scratch (device globals; zero-initialized at load) ----
__device__ float  d_q[NMAX];        // q[n] = dinv[n] * (u . p[n] + c2)
__device__ float  d_sacc[NMAX];     // scalar accumulator, init = q (self loop)
__device__ float  d_dinv[NMAX];
__device__ int    d_deg[NMAX];      // starts 0; encode_k re-zeroes after read
__device__ double d_part[NBN][5];   // per-block x-moment partials
__device__ float  d_C;              // wb . gcn_b + bb

// ---------------------------------------------------------------------------
// degstats_k: in-degree histogram (8 edges/thread) + x-moment partials.
// Default cache policy on dst: it is re-read by scatter_k and fits in L2.
__global__ void __launch_bounds__(256) degstats_k(
    const int* __restrict__ dst, int nT8, int Etail,
    const float* __restrict__ x, int n, int nbn) {
    int t = threadIdx.x;
    int i = blockIdx.x * 256 + t;
    if (i < nT8) {
        const int4* d4 = (const int4*)dst;
        int4 a = d4[2 * i];
        int4 b = d4[2 * i + 1];
        atomicAdd(&d_deg[a.x], 1); atomicAdd(&d_deg[a.y], 1);
        atomicAdd(&d_deg[a.z], 1); atomicAdd(&d_deg[a.w], 1);
        atomicAdd(&d_deg[b.x], 1); atomicAdd(&d_deg[b.y], 1);
        atomicAdd(&d_deg[b.z], 1); atomicAdd(&d_deg[b.w], 1);
    }
    if (i == 0)
        for (int k = 0; k < Etail; k++) atomicAdd(&d_deg[dst[nT8 * 8 + k]], 1);

    // stats: first nbn blocks, one node per thread
    if (blockIdx.x < nbn) {
        __shared__ double sred[8][5];
        int node = blockIdx.x * 256 + t;
        float a = 0.f, b = 0.f;
        if (node < n) {
            float2 xv = ((const float2*)x)[node];
            a = xv.x; b = xv.y;
        }
        float s[5] = { a, b, a * a, b * b, a * b };
#pragma unroll
        for (int o = 16; o; o >>= 1)
#pragma unroll
            for (int j = 0; j < 5; j++) s[j] += __shfl_xor_sync(0xffffffffu, s[j], o);
        if ((t & 31) == 0)
#pragma unroll
            for (int j = 0; j < 5; j++) sred[t >> 5][j] = (double)s[j];
        __syncthreads();
        if (t < 5) {
            double acc = 0.0;
#pragma unroll
            for (int w = 0; w < 8; w++) acc += sred[w][t];
            d_part[blockIdx.x][t] = acc;
        }
    }
}

// encode_k: fold BN/v/u/c2/C, compute q per node, re-zero deg for next replay
__global__ void __launch_bounds__(256) encode_k(
    const float* __restrict__ x,
    const float* __restrict__ w1, const float* __restrict__ b1,
    const float* __restrict__ gam, const float* __restrict__ bet,
    const float* __restrict__ pa,
    const float* __restrict__ w2, const float* __restrict__ b2,
    const float* __restrict__ gw, const float* __restrict__ gb,
    const float* __restrict__ wb, const float* __restrict__ bb,
    int n, int nbn) {
    __shared__ float sA[2 * D], sB[D], sU[D], sV[D];
    __shared__ float sc2;
    __shared__ double sst[5];
    int t = threadIdx.x;

    // parallel reduce of stats partials: warp c (0..4) owns component c
    if (t < 160) {
        int c = t >> 5, k = t & 31;
        double a = 0.0;
        for (int b = k; b < nbn; b += 32) a += d_part[b][c];
#pragma unroll
        for (int o = 16; o; o >>= 1) a += __shfl_xor_sync(0xffffffffu, a, o);
        if (k == 0) sst[c] = a;
    }
    __syncthreads();

    if (t < D) {
        double invN = 1.0 / (double)n;
        double m0 = sst[0] * invN, m1 = sst[1] * invN;
        double v00 = sst[2] * invN - m0 * m0;
        double v11 = sst[3] * invN - m1 * m1;
        double v01 = sst[4] * invN - m0 * m1;
        float a0 = w1[2 * t], a1 = w1[2 * t + 1];
        float mean = (float)((double)a0 * m0 + (double)a1 * m1) + b1[t];
        float var  = (float)((double)a0 * a0 * v00 + 2.0 * (double)a0 * a1 * v01 +
                             (double)a1 * a1 * v11);
        float scale = gam[t] * rsqrtf(var + 1e-5f);
        sA[2 * t]     = a0 * scale;
        sA[2 * t + 1] = a1 * scale;
        sB[t] = b1[t] * scale + bet[t] - mean * scale;
        float v = 0.f;
#pragma unroll
        for (int r = 0; r < D; r++) v = fmaf(wb[r], gw[r * D + t], v);
        sV[t] = v;
    }
    __syncthreads();
    if (t < D) {
        float u = 0.f;
#pragma unroll
        for (int r = 0; r < D; r++) u = fmaf(sV[r], w2[r * D + t], u);
        sU[t] = u;
        float cc = sV[t] * b2[t];
        float Cc = wb[t] * gb[t];
#pragma unroll
        for (int o = 16; o; o >>= 1) {
            cc += __shfl_xor_sync(0xffffffffu, cc, o);
            Cc += __shfl_xor_sync(0xffffffffu, Cc, o);
        }
        if (t == 0) {
            sc2 = cc;
            if (blockIdx.x == 0) d_C = Cc + bb[0];
        }
    }
    __syncthreads();

    int node = blockIdx.x * 256 + t;
    if (node < n) {
        float2 xv = ((const float2*)x)[node];
        float alpha = pa[0];
        int dg = d_deg[node];
        d_deg[node] = 0;                      // re-zero for next graph replay
        float dv = rsqrtf((float)dg + 1.0f);
        float acc = sc2;
#pragma unroll
        for (int k = 0; k < D; k++) {
            float h = fmaf(sA[2 * k], xv.x, fmaf(sA[2 * k + 1], xv.y, sB[k]));
            float p = h >= 0.f ? h : alpha * h;
            acc = fmaf(sU[k], p, acc);
        }
        float qv = dv * acc;
        d_q[node] = qv;
        d_sacc[node] = qv;                    // self-loop prefolded
        d_dinv[node] = dv;
    }
}

// scatter_k: 8 edges/thread, fully batched (indices -> gathers -> REDs)
__global__ void __launch_bounds__(256) scatter_k(const int* __restrict__ ei, int E,
                                                 int nT8, int Etail) {
    int i = blockIdx.x * 256 + threadIdx.x;
    if (i < nT8) {
        const int4* s4 = (const int4*)ei;
        const int4* d4 = (const int4*)(ei + E);   // L2-hot from degstats_k
        int4 s0 = s4[2 * i];
        int4 s1 = s4[2 * i + 1];
        int4 t0 = d4[2 * i];
        int4 t1 = d4[2 * i + 1];
        float q0 = __ldg(&d_q[s0.x]);
        float q1 = __ldg(&d_q[s0.y]);
        float q2 = __ldg(&d_q[s0.z]);
        float q3 = __ldg(&d_q[s0.w]);
        float q4 = __ldg(&d_q[s1.x]);
        float q5 = __ldg(&d_q[s1.y]);
        float q6 = __ldg(&d_q[s1.z]);
        float q7 = __ldg(&d_q[s1.w]);
        atomicAdd(&d_sacc[t0.x], q0);
        atomicAdd(&d_sacc[t0.y], q1);
        atomicAdd(&d_sacc[t0.z], q2);
        atomicAdd(&d_sacc[t0.w], q3);
        atomicAdd(&d_sacc[t1.x], q4);
        atomicAdd(&d_sacc[t1.y], q5);
        atomicAdd(&d_sacc[t1.z], q6);
        atomicAdd(&d_sacc[t1.w], q7);
    }
    if (i == 0)
        for (int k = 0; k < Etail; k++) {
            int e = nT8 * 8 + k;
            atomicAdd(&d_sacc[ei[E + e]], __ldg(&d_q[ei[e]]));
        }
}

// score_k: out[n] = C + dinv[n] * sacc[n], float4-vectorized, 128-thr blocks
__global__ void __launch_bounds__(128) score_k(float* __restrict__ out, int n4, int n) {
    int i = blockIdx.x * 128 + threadIdx.x;
    if (i < n4) {
        float4 dv = ((const float4*)d_dinv)[i];
        float4 sa = ((const float4*)d_sacc)[i];
        float C = d_C;
        float4 o;
        o.x = fmaf(dv.x, sa.x, C);
        o.y = fmaf(dv.y, sa.y, C);
        o.z = fmaf(dv.z, sa.z, C);
        o.w = fmaf(dv.w, sa.w, C);
        ((float4*)out)[i] = o;
    }
    if (i == 0)
        for (int k = n4 * 4; k < n; k++) out[k] = fmaf(d_dinv[k], d_sacc[k], d_C);
}

// ---------------------------------------------------------------------------
extern "C" void kernel_launch(void* const* d_in, const int* in_sizes, int n_in,
                              void* d_out, int out_size) {
    const float* x   = (const float*)d_in[0];
    const int*   ei  = (const int*)d_in[1];      // int32 (JAX x64 disabled)
    const float* w1  = (const float*)d_in[2];
    const float* b1  = (const float*)d_in[3];
    const float* gam = (const float*)d_in[4];
    const float* bet = (const float*)d_in[5];
    const float* pa  = (const float*)d_in[6];
    const float* w2  = (const float*)d_in[7];
    const float* b2  = (const float*)d_in[8];
    const float* gw  = (const float*)d_in[9];
    const float* gb  = (const float*)d_in[10];
    const float* wb  = (const float*)d_in[11];
    const float* bb  = (const float*)d_in[12];
    int n = in_sizes[0] / 2;
    int E = in_sizes[1] / 2;
    int nT8 = E >> 3;                 // 8 edges per thread
    int Etail = E & 7;
    int nbn = (n + 255) / 256;
    int ebn = (nT8 + 255) / 256;
    if (ebn < nbn) ebn = nbn;         // edge grid must cover the stats blocks
    int n4 = n >> 2;

    degstats_k<<<ebn, 256>>>(ei + E, nT8, Etail, x, n, nbn);
    encode_k<<<nbn, 256>>>(x, w1, b1, gam, bet, pa, w2, b2, gw, gb, wb, bb, n, nbn);
    scatter_k<<<(nT8 + 255) / 256, 256>>>(ei, E, nT8, Etail);
    score_k<<<(n4 + 127) / 128, 128>>>((float*)d_out, n4, n);
}